// round 12
// baseline (speedup 1.0000x reference)
#include <cuda_runtime.h>
#include <cuda_bf16.h>
#include <cstdint>

// entmax-1.5 attention, B=2 H=8 S=2048 D=64 fp32.
//  prep: Q,K fp32 -> bf16 hi/lo concat (K=192: [Qh|Qh|Ql] x [Kh|Kl|Kh])
//  k1:   exact-bf16-split HMMA GEMM + fused candidate filter -> g_cand
//        3-stage cp.async K ring, 512 threads, fragment double buffering
//  k2:   per-row entmax on candidates (REGC=8, occ 4) + sparse P*V

#define SL   2048
#define DD   64
#define NBH  16
#define KCAT 192
#define RB   400

__device__ float2 g_cand[(size_t)NBH * SL * SL];             // hard bound
__device__ int    g_cnt[NBH * SL];
__device__ uint4  g_qcat4[(size_t)NBH * SL * KCAT * 2 / 16];
__device__ uint4  g_kcat4[(size_t)NBH * SL * KCAT * 2 / 16];

__device__ __forceinline__ uint32_t smem_u32(const void* p) {
    uint32_t a;
    asm("{ .reg .u64 t; cvta.to.shared.u64 t, %1; cvt.u32.u64 %0, t; }"
        : "=r"(a) : "l"(p));
    return a;
}
#define CP16(d, s) asm volatile("cp.async.cg.shared.global [%0], [%1], 16;" :: "r"(d), "l"(s) : "memory")
#define CP_COMMIT() asm volatile("cp.async.commit_group;" ::: "memory")
#define CP_WAIT(n)  asm volatile("cp.async.wait_group %0;" :: "n"(n) : "memory")
#define LDSM_X4(r, a)                                                          \
    asm volatile("ldmatrix.sync.aligned.m8n8.x4.shared.b16 {%0,%1,%2,%3}, [%4];" \
        : "=r"((r)[0]), "=r"((r)[1]), "=r"((r)[2]), "=r"((r)[3]) : "r"(a))

__device__ __forceinline__ void mma_bf16(float* c, const uint32_t* a,
                                         uint32_t b0, uint32_t b1) {
    asm volatile(
        "mma.sync.aligned.m16n8k16.row.col.f32.bf16.bf16.f32 "
        "{%0,%1,%2,%3}, {%4,%5,%6,%7}, {%8,%9}, {%0,%1,%2,%3};"
        : "+f"(c[0]), "+f"(c[1]), "+f"(c[2]), "+f"(c[3])
        : "r"(a[0]), "r"(a[1]), "r"(a[2]), "r"(a[3]), "r"(b0), "r"(b1));
}

__device__ __forceinline__ unsigned encf(float x) {
    unsigned u = __float_as_uint(x);
    return u ^ (unsigned)(((int)u >> 31) | 0x80000000);
}
__device__ __forceinline__ float decf(unsigned e) {
    unsigned u = (e & 0x80000000u) ? (e ^ 0x80000000u) : ~e;
    return __uint_as_float(u);
}

// ---------------------------------------------------------------------------
// dummy: shifts the ncu capture slot so k1 gets profiled
// ---------------------------------------------------------------------------
__global__ void dummy_kernel() {}

// ---------------------------------------------------------------------------
// prep: build bf16 concat tensors
// ---------------------------------------------------------------------------
__global__ void __launch_bounds__(256)
prep_kernel(const float* __restrict__ q, const float* __restrict__ k)
{
    int gid = blockIdx.x * 256 + threadIdx.x;
    int tensor = gid >> 18;
    int rem = gid & ((1 << 18) - 1);
    int r = rem >> 3, g = rem & 7;
    const float* src = (tensor ? k : q) + (size_t)r * DD + g * 8;
    __nv_bfloat16* dst = (__nv_bfloat16*)(tensor ? g_kcat4 : g_qcat4) + (size_t)r * KCAT;

    float4 a = ((const float4*)src)[0];
    float4 b = ((const float4*)src)[1];
    float xs[8] = {a.x, a.y, a.z, a.w, b.x, b.y, b.z, b.w};
    __align__(16) __nv_bfloat16 hi[8], lo[8];
#pragma unroll
    for (int i = 0; i < 8; i++) {
        hi[i] = __float2bfloat16(xs[i]);
        lo[i] = __float2bfloat16(xs[i] - __bfloat162float(hi[i]));
    }
    *(uint4*)(dst + g * 8) = *(const uint4*)hi;
    if (tensor == 0) {
        *(uint4*)(dst + 64 + g * 8)  = *(const uint4*)hi;
        *(uint4*)(dst + 128 + g * 8) = *(const uint4*)lo;
    } else {
        *(uint4*)(dst + 64 + g * 8)  = *(const uint4*)lo;
        *(uint4*)(dst + 128 + g * 8) = *(const uint4*)hi;
    }
}

// ---------------------------------------------------------------------------
// k1: exact HMMA GEMM + fused filter. CTA = 128 q x 2048 keys, 512 threads.
//     smem: A (51.2KB) + 3-stage K ring (3 x 51.2KB) = 204.8KB, occ 1.
//     16 warps, warp tile 32x32, fragment double buffering across ks.
// ---------------------------------------------------------------------------
#define NT1 512
#define KTILE (128 * RB)
#define OFF_A 0
#define SMEM1_TOTAL (4 * KTILE)

__global__ void __launch_bounds__(NT1, 1)
qk_mma_kernel()
{
    extern __shared__ char smem[];
    __shared__ unsigned s_runmax[128];
    __shared__ int s_cnt[128];
    __shared__ int s_part[128][17];

    const uint32_t sb = smem_u32(smem);
    const int tid = threadIdx.x, warp = tid >> 5, lane = tid & 31;

    const int bh = blockIdx.y;
    const int q0 = blockIdx.x * 128;
    const size_t rid0 = (size_t)bh * SL + q0;
    const uint4* __restrict__ qc = g_qcat4 + rid0 * (KCAT / 8);
    const uint4* __restrict__ kc = g_kcat4 + (size_t)bh * SL * (KCAT / 8);

    if (tid < 128) { s_runmax[tid] = encf(-3e38f); s_cnt[tid] = 0; }

    // prologue: group0 = A + K0, group1 = K1
#pragma unroll
    for (int u = 0; u < 6; u++) {
        int idx = tid + u * NT1;
        int row = idx / 24, cc = idx % 24;
        CP16(sb + OFF_A + row * RB + cc * 16, qc + idx);
        CP16(sb + KTILE + row * RB + cc * 16, kc + idx);
    }
    CP_COMMIT();
    {
        const uint4* src = kc + (size_t)128 * (KCAT / 8);
#pragma unroll
        for (int u = 0; u < 6; u++) {
            int idx = tid + u * NT1;
            int row = idx / 24, cc = idx % 24;
            CP16(sb + KTILE * 2 + row * RB + cc * 16, src + idx);
        }
    }
    CP_COMMIT();

    const int wm = warp & 3;     // M tile of 32
    const int wn = warp >> 2;    // N tile of 32
    const int oid = wn * 4 + (lane & 3);

    const uint32_t a_base = sb + OFF_A +
        (uint32_t)(wm * 32 + (lane & 15)) * RB + (lane >> 4) * 16;
    const uint32_t b_row = (uint32_t)(wn * 32 + lane) * RB;

    float acc[2][4][4];
#pragma unroll
    for (int mt = 0; mt < 2; mt++)
#pragma unroll
        for (int nt = 0; nt < 4; nt++)
#pragma unroll
            for (int i = 0; i < 4; i++) acc[mt][nt][i] = 0.f;

    for (int c = 0; c < 16; c++) {
        if (c == 15) { CP_WAIT(0); } else { CP_WAIT(1); }
        __syncthreads();   // also: all warps done reading buf[(c+2)%3]

        if (c < 14) {
            const uint32_t nb = sb + KTILE * (1 + (c + 2) % 3);
            const uint4* src = kc + (size_t)(c + 2) * 128 * (KCAT / 8);
#pragma unroll
            for (int u = 0; u < 6; u++) {
                int idx = tid + u * NT1;
                int row = idx / 24, cc = idx % 24;
                CP16(nb + row * RB + cc * 16, src + idx);
            }
            CP_COMMIT();
        }

        const uint32_t cur = sb + KTILE * (1 + c % 3);

        // ---- 128x128x192, warp tile 32x32, frag double buffering ----
        uint32_t af[2][2][4], bf[2][2][4];   // [buf][mt/ko][4]
        // load ks=0 fragments
#pragma unroll
        for (int mt = 0; mt < 2; mt++)
            LDSM_X4(af[0][mt], a_base + mt * 16 * RB);
#pragma unroll
        for (int ko = 0; ko < 2; ko++)
            LDSM_X4(bf[0][ko], cur + b_row + ko * 16);

#pragma unroll
        for (int ks = 0; ks < 12; ks++) {
            const int cb = ks & 1, nbf = cb ^ 1;
            if (ks < 11) {   // prefetch ks+1 fragments before MMAs
#pragma unroll
                for (int mt = 0; mt < 2; mt++)
                    LDSM_X4(af[nbf][mt], a_base + mt * 16 * RB + (ks + 1) * 32);
#pragma unroll
                for (int ko = 0; ko < 2; ko++)
                    LDSM_X4(bf[nbf][ko], cur + b_row + (ks + 1) * 32 + ko * 16);
            }
#pragma unroll
            for (int mt = 0; mt < 2; mt++)
#pragma unroll
                for (int nt = 0; nt < 4; nt++)
                    mma_bf16(acc[mt][nt], af[cb][mt], bf[cb][0][nt], bf[cb][1][nt]);
        }

        // ---- fused filter epilogue ----
        // A) per-row running max
#pragma unroll
        for (int mt = 0; mt < 2; mt++)
#pragma unroll
            for (int h = 0; h < 2; h++) {
                float m = -3e38f;
#pragma unroll
                for (int nt = 0; nt < 4; nt++)
                    m = fmaxf(m, fmaxf(acc[mt][nt][h * 2], acc[mt][nt][h * 2 + 1]));
                int lr = wm * 32 + mt * 16 + h * 8 + (lane >> 2);
                atomicMax(&s_runmax[lr], encf(m * 0.125f));
            }
        __syncthreads();

        // B) predicate + per-owner counts
        unsigned pm[2][2];
#pragma unroll
        for (int mt = 0; mt < 2; mt++)
#pragma unroll
            for (int h = 0; h < 2; h++) {
                int lr = wm * 32 + mt * 16 + h * 8 + (lane >> 2);
                float thr = decf(s_runmax[lr]) - 2.0f;
                unsigned msk = 0;
#pragma unroll
                for (int nt = 0; nt < 4; nt++)
#pragma unroll
                    for (int ic = 0; ic < 2; ic++)
                        if (acc[mt][nt][h * 2 + ic] * 0.125f > thr)
                            msk |= 1u << (nt * 2 + ic);
                pm[mt][h] = msk;
                s_part[lr][oid] = __popc(msk);
            }
        __syncthreads();

        // C) deterministic per-row prefix over 16 owners
        if (tid < 128) {
            int b = s_cnt[tid];
#pragma unroll
            for (int o = 0; o < 16; o++) {
                int t = s_part[tid][o];
                s_part[tid][o] = b;
                b += t;
            }
            s_cnt[tid] = b;
        }
        __syncthreads();

        // D) append candidates at deterministic positions
#pragma unroll
        for (int mt = 0; mt < 2; mt++)
#pragma unroll
            for (int h = 0; h < 2; h++) {
                int lr = wm * 32 + mt * 16 + h * 8 + (lane >> 2);
                unsigned msk = pm[mt][h];
                int pos = s_part[lr][oid];
                size_t base = (rid0 + lr) * (size_t)SL;
#pragma unroll
                for (int nt = 0; nt < 4; nt++)
#pragma unroll
                    for (int ic = 0; ic < 2; ic++) {
                        if (msk & (1u << (nt * 2 + ic))) {
                            int col = c * 128 + wn * 32 + nt * 8 + (lane & 3) * 2 + ic;
                            g_cand[base + pos] = make_float2(
                                acc[mt][nt][h * 2 + ic] * 0.125f,
                                __int_as_float(col));
                            pos++;
                        }
                        acc[mt][nt][h * 2 + ic] = 0.f;
                    }
            }
    }

    __syncthreads();
    if (tid < 128) g_cnt[rid0 + tid] = s_cnt[tid];
}

// ---------------------------------------------------------------------------
// k2: entmax on candidates + sparse P*V. One warp per row.
// ---------------------------------------------------------------------------
#define NEWT 6
#define NCF  3
#define CAPL 128
#define REGC 8            // 256 reg-resident candidates (covers ~all rows)

__global__ void __launch_bounds__(256, 4)
entmax_pv3_kernel(const float* __restrict__ v, float* __restrict__ out)
{
    __shared__ float sp[8][CAPL];
    __shared__ int   si[8][CAPL];

    const int tid = threadIdx.x, warp = tid >> 5, lane = tid & 31;
    const int rid = blockIdx.x * 8 + warp;
    const int cnt = g_cnt[rid];
    const float2* __restrict__ cand = g_cand + (size_t)rid * SL;
    const float* __restrict__ vb = v + (size_t)(rid >> 11) * SL * DD;

    float xs[REGC];
#pragma unroll
    for (int j = 0; j < REGC; j++) {
        int idx = j * 32 + lane;
        xs[j] = (idx < cnt) ? cand[idx].x : -1e30f;
    }
    const bool big = (cnt > REGC * 32);

    float mx = -3e38f;
#pragma unroll
    for (int j = 0; j < REGC; j++) mx = fmaxf(mx, xs[j]);
    if (big)
        for (int idx = REGC * 32 + lane; idx < cnt; idx += 32)
            mx = fmaxf(mx, cand[idx].x);
#pragma unroll
    for (int o = 16; o; o >>= 1)
        mx = fmaxf(mx, __shfl_xor_sync(0xffffffffu, mx, o));
#pragma unroll
    for (int j = 0; j < REGC; j++) xs[j] = (xs[j] - mx) * 0.5f;

    // Newton from below (tau0 = -1 guarantees f >= 1; non-candidates have
    // x <= -1 <= tau and contribute exactly 0 -> result is exact)
    float tau = -1.0f;
    for (int it = 0; it < NEWT; it++) {
        float f = 0.f, g = 0.f;
#pragma unroll
        for (int j = 0; j < REGC; j++) {
            float m = fmaxf(xs[j] - tau, 0.f);
            f = fmaf(m, m, f); g += m;
        }
        if (big)
            for (int idx = REGC * 32 + lane; idx < cnt; idx += 32) {
                float xv = (cand[idx].x - mx) * 0.5f;
                float m = fmaxf(xv - tau, 0.f);
                f = fmaf(m, m, f); g += m;
            }
#pragma unroll
        for (int o = 16; o; o >>= 1) {
            f += __shfl_xor_sync(0xffffffffu, f, o);
            g += __shfl_xor_sync(0xffffffffu, g, o);
        }
        tau += (f - 1.0f) / fmaxf(2.0f * g, 1e-20f);
    }

    // closed-form refinement on current support (exact fixed point)
    for (int p = 0; p < NCF; p++) {
        float n = 0.f, s = 0.f, qq = 0.f;
#pragma unroll
        for (int j = 0; j < REGC; j++) {
            if (xs[j] > tau) { n += 1.f; s += xs[j]; qq = fmaf(xs[j], xs[j], qq); }
        }
        if (big)
            for (int idx = REGC * 32 + lane; idx < cnt; idx += 32) {
                float xv = (cand[idx].x - mx) * 0.5f;
                if (xv > tau) { n += 1.f; s += xv; qq = fmaf(xv, xv, qq); }
            }
#pragma unroll
        for (int o = 16; o; o >>= 1) {
            n  += __shfl_xor_sync(0xffffffffu, n, o);
            s  += __shfl_xor_sync(0xffffffffu, s, o);
            qq += __shfl_xor_sync(0xffffffffu, qq, o);
        }
        float disc = fmaxf(s * s - n * (qq - 1.0f), 0.f);
        tau = (s - sqrtf(disc)) / fmaxf(n, 1.0f);
    }

    // support extraction (ballot-compacted, deterministic order) + V gather
    float acc0 = 0.f, acc1 = 0.f, ps = 0.f;
    const unsigned lt = (1u << lane) - 1u;
    int off = 0;

#pragma unroll
    for (int j = 0; j < REGC; j++) {
        float m = xs[j] - tau;
        bool act = (m > 0.f);
        unsigned mask = __ballot_sync(0xffffffffu, act);
        int c = __popc(mask);
        if (off + c > CAPL) {
            __syncwarp();
            for (int t = 0; t < off; t++) {
                float pv = sp[warp][t];
                int key = si[warp][t];
                acc0 = fmaf(pv, vb[key * DD + lane], acc0);
                acc1 = fmaf(pv, vb[key * DD + 32 + lane], acc1);
            }
            __syncwarp();
            off = 0;
        }
        if (act) {
            int pos = off + __popc(mask & lt);
            float pv = m * m;
            sp[warp][pos] = pv;
            si[warp][pos] = __float_as_int(cand[j * 32 + lane].y);
            ps += pv;
        }
        off += c;
    }
    if (big) {
        for (int bix = REGC * 32; bix < cnt; bix += 32) {
            int idx = bix + lane;
            bool valid = idx < cnt;
            float2 t2 = valid ? cand[idx] : make_float2(-1e30f, 0.f);
            float m = (t2.x - mx) * 0.5f - tau;
            bool act = valid && (m > 0.f);
            unsigned mask = __ballot_sync(0xffffffffu, act);
            int c = __popc(mask);
            if (off + c > CAPL) {
                __syncwarp();
                for (int t = 0; t < off; t++) {
                    float pv = sp[warp][t];
                    int key = si[warp][t];
                    acc0 = fmaf(pv, vb[key * DD + lane], acc0);
                    acc1 = fmaf(pv, vb[key * DD + 32 + lane], acc1);
                }
                __syncwarp();
                off = 0;
            }
            if (act) {
                int pos = off + __popc(mask & lt);
                float pv = m * m;
                sp[warp][pos] = pv;
                si[warp][pos] = __float_as_int(t2.y);
                ps += pv;
            }
            off += c;
        }
    }
    __syncwarp();
    for (int t = 0; t < off; t++) {
        float pv = sp[warp][t];
        int key = si[warp][t];
        acc0 = fmaf(pv, vb[key * DD + lane], acc0);
        acc1 = fmaf(pv, vb[key * DD + 32 + lane], acc1);
    }

    // renormalize (first-order tau error cancellation)
#pragma unroll
    for (int o = 16; o; o >>= 1)
        ps += __shfl_xor_sync(0xffffffffu, ps, o);
    float inv = 1.0f / fmaxf(ps, 1e-20f);

    float* orow = out + (size_t)rid * DD;
    orow[lane]      = acc0 * inv;
    orow[lane + 32] = acc1 * inv;
}

// ---------------------------------------------------------------------------
extern "C" void kernel_launch(void* const* d_in, const int* in_sizes, int n_in,
                              void* d_out, int out_size)
{
    const float* q = (const float*)d_in[0];
    const float* k = (const float*)d_in[1];
    const float* v = (const float*)d_in[2];
    float* out = (float*)d_out;

    dummy_kernel<<<1, 32>>>();   // shifts ncu capture slot toward qk_mma

    prep_kernel<<<2048, 256>>>(q, k);

    cudaFuncSetAttribute(qk_mma_kernel,
                         cudaFuncAttributeMaxDynamicSharedMemorySize, SMEM1_TOTAL);
    dim3 g1(SL / 128, NBH);
    qk_mma_kernel<<<g1, NT1, SMEM1_TOTAL>>>();

    entmax_pv3_kernel<<<(NBH * SL) / 8, 256>>>(v, out);
}

// round 15
// speedup vs baseline: 1.0186x; 1.0186x over previous
#include <cuda_runtime.h>
#include <cuda_bf16.h>
#include <cstdint>

// entmax-1.5 attention, B=2 H=8 S=2048 D=64 fp32.
//  prep: Q,K fp32 -> bf16 hi/lo concat (K=192: [Qh|Qh|Ql] x [Kh|Kl|Kh])
//  k1:   exact-bf16-split HMMA GEMM + fused candidate filter -> g_cand
//  k2:   per-row entmax on candidates + sparse P*V (128thr x 9 blocks,
//        float2 V gather, fused (p,key) list)

#define SL   2048
#define DD   64
#define NBH  16
#define KCAT 192
#define RB   400

__device__ float2 g_cand[(size_t)NBH * SL * SL];             // hard bound
__device__ int    g_cnt[NBH * SL];
__device__ uint4  g_qcat4[(size_t)NBH * SL * KCAT * 2 / 16];
__device__ uint4  g_kcat4[(size_t)NBH * SL * KCAT * 2 / 16];

__device__ __forceinline__ uint32_t smem_u32(const void* p) {
    uint32_t a;
    asm("{ .reg .u64 t; cvta.to.shared.u64 t, %1; cvt.u32.u64 %0, t; }"
        : "=r"(a) : "l"(p));
    return a;
}
#define CP16(d, s) asm volatile("cp.async.cg.shared.global [%0], [%1], 16;" :: "r"(d), "l"(s) : "memory")
#define CP_COMMIT() asm volatile("cp.async.commit_group;" ::: "memory")
#define CP_WAIT(n)  asm volatile("cp.async.wait_group %0;" :: "n"(n) : "memory")
#define LDSM_X4(r, a)                                                          \
    asm volatile("ldmatrix.sync.aligned.m8n8.x4.shared.b16 {%0,%1,%2,%3}, [%4];" \
        : "=r"((r)[0]), "=r"((r)[1]), "=r"((r)[2]), "=r"((r)[3]) : "r"(a))

__device__ __forceinline__ void mma_bf16(float* c, const uint32_t* a,
                                         uint32_t b0, uint32_t b1) {
    asm volatile(
        "mma.sync.aligned.m16n8k16.row.col.f32.bf16.bf16.f32 "
        "{%0,%1,%2,%3}, {%4,%5,%6,%7}, {%8,%9}, {%0,%1,%2,%3};"
        : "+f"(c[0]), "+f"(c[1]), "+f"(c[2]), "+f"(c[3])
        : "r"(a[0]), "r"(a[1]), "r"(a[2]), "r"(a[3]), "r"(b0), "r"(b1));
}

__device__ __forceinline__ unsigned encf(float x) {
    unsigned u = __float_as_uint(x);
    return u ^ (unsigned)(((int)u >> 31) | 0x80000000);
}
__device__ __forceinline__ float decf(unsigned e) {
    unsigned u = (e & 0x80000000u) ? (e ^ 0x80000000u) : ~e;
    return __uint_as_float(u);
}

// ---------------------------------------------------------------------------
// dummies: shift the ncu capture slot so qk_mma gets profiled
// ---------------------------------------------------------------------------
__global__ void dummy_kernel() {}
__global__ void dummy_kernel2() {}

// ---------------------------------------------------------------------------
// prep: build bf16 concat tensors
// ---------------------------------------------------------------------------
__global__ void __launch_bounds__(256)
prep_kernel(const float* __restrict__ q, const float* __restrict__ k)
{
    int gid = blockIdx.x * 256 + threadIdx.x;
    int tensor = gid >> 18;
    int rem = gid & ((1 << 18) - 1);
    int r = rem >> 3, g = rem & 7;
    const float* src = (tensor ? k : q) + (size_t)r * DD + g * 8;
    __nv_bfloat16* dst = (__nv_bfloat16*)(tensor ? g_kcat4 : g_qcat4) + (size_t)r * KCAT;

    float4 a = ((const float4*)src)[0];
    float4 b = ((const float4*)src)[1];
    float xs[8] = {a.x, a.y, a.z, a.w, b.x, b.y, b.z, b.w};
    __align__(16) __nv_bfloat16 hi[8], lo[8];
#pragma unroll
    for (int i = 0; i < 8; i++) {
        hi[i] = __float2bfloat16(xs[i]);
        lo[i] = __float2bfloat16(xs[i] - __bfloat162float(hi[i]));
    }
    *(uint4*)(dst + g * 8) = *(const uint4*)hi;
    if (tensor == 0) {
        *(uint4*)(dst + 64 + g * 8)  = *(const uint4*)hi;
        *(uint4*)(dst + 128 + g * 8) = *(const uint4*)lo;
    } else {
        *(uint4*)(dst + 64 + g * 8)  = *(const uint4*)lo;
        *(uint4*)(dst + 128 + g * 8) = *(const uint4*)hi;
    }
}

// ---------------------------------------------------------------------------
// k1: exact HMMA GEMM + fused filter. CTA = 128 q x 2048 keys, 512 threads.
//     smem: A (51.2KB) + 3-stage K ring (3 x 51.2KB) = 204.8KB, occ 1.
// ---------------------------------------------------------------------------
#define NT1 512
#define KTILE (128 * RB)
#define OFF_A 0
#define SMEM1_TOTAL (4 * KTILE)

__global__ void __launch_bounds__(NT1, 1)
qk_mma_kernel()
{
    extern __shared__ char smem[];
    __shared__ unsigned s_runmax[128];
    __shared__ int s_cnt[128];
    __shared__ int s_part[128][17];

    const uint32_t sb = smem_u32(smem);
    const int tid = threadIdx.x, warp = tid >> 5, lane = tid & 31;

    const int bh = blockIdx.y;
    const int q0 = blockIdx.x * 128;
    const size_t rid0 = (size_t)bh * SL + q0;
    const uint4* __restrict__ qc = g_qcat4 + rid0 * (KCAT / 8);
    const uint4* __restrict__ kc = g_kcat4 + (size_t)bh * SL * (KCAT / 8);

    if (tid < 128) { s_runmax[tid] = encf(-3e38f); s_cnt[tid] = 0; }

    // prologue: group0 = A + K0, group1 = K1
#pragma unroll
    for (int u = 0; u < 6; u++) {
        int idx = tid + u * NT1;
        int row = idx / 24, cc = idx % 24;
        CP16(sb + OFF_A + row * RB + cc * 16, qc + idx);
        CP16(sb + KTILE + row * RB + cc * 16, kc + idx);
    }
    CP_COMMIT();
    {
        const uint4* src = kc + (size_t)128 * (KCAT / 8);
#pragma unroll
        for (int u = 0; u < 6; u++) {
            int idx = tid + u * NT1;
            int row = idx / 24, cc = idx % 24;
            CP16(sb + KTILE * 2 + row * RB + cc * 16, src + idx);
        }
    }
    CP_COMMIT();

    const int wm = warp & 3;     // M tile of 32
    const int wn = warp >> 2;    // N tile of 32
    const int oid = wn * 4 + (lane & 3);

    const uint32_t a_base = sb + OFF_A +
        (uint32_t)(wm * 32 + (lane & 15)) * RB + (lane >> 4) * 16;
    const uint32_t b_row = (uint32_t)(wn * 32 + lane) * RB;

    float acc[2][4][4];
#pragma unroll
    for (int mt = 0; mt < 2; mt++)
#pragma unroll
        for (int nt = 0; nt < 4; nt++)
#pragma unroll
            for (int i = 0; i < 4; i++) acc[mt][nt][i] = 0.f;

    for (int c = 0; c < 16; c++) {
        if (c == 15) { CP_WAIT(0); } else { CP_WAIT(1); }
        __syncthreads();   // also: all warps done reading buf[(c+2)%3]

        if (c < 14) {
            const uint32_t nb = sb + KTILE * (1 + (c + 2) % 3);
            const uint4* src = kc + (size_t)(c + 2) * 128 * (KCAT / 8);
#pragma unroll
            for (int u = 0; u < 6; u++) {
                int idx = tid + u * NT1;
                int row = idx / 24, cc = idx % 24;
                CP16(nb + row * RB + cc * 16, src + idx);
            }
            CP_COMMIT();
        }

        const uint32_t cur = sb + KTILE * (1 + c % 3);

        // ---- 128x128x192, warp tile 32x32, frag double buffering ----
        uint32_t af[2][2][4], bf[2][2][4];
#pragma unroll
        for (int mt = 0; mt < 2; mt++)
            LDSM_X4(af[0][mt], a_base + mt * 16 * RB);
#pragma unroll
        for (int ko = 0; ko < 2; ko++)
            LDSM_X4(bf[0][ko], cur + b_row + ko * 16);

#pragma unroll
        for (int ks = 0; ks < 12; ks++) {
            const int cb = ks & 1, nbf = cb ^ 1;
            if (ks < 11) {
#pragma unroll
                for (int mt = 0; mt < 2; mt++)
                    LDSM_X4(af[nbf][mt], a_base + mt * 16 * RB + (ks + 1) * 32);
#pragma unroll
                for (int ko = 0; ko < 2; ko++)
                    LDSM_X4(bf[nbf][ko], cur + b_row + (ks + 1) * 32 + ko * 16);
            }
#pragma unroll
            for (int mt = 0; mt < 2; mt++)
#pragma unroll
                for (int nt = 0; nt < 4; nt++)
                    mma_bf16(acc[mt][nt], af[cb][mt], bf[cb][0][nt], bf[cb][1][nt]);
        }

        // ---- fused filter epilogue ----
#pragma unroll
        for (int mt = 0; mt < 2; mt++)
#pragma unroll
            for (int h = 0; h < 2; h++) {
                float m = -3e38f;
#pragma unroll
                for (int nt = 0; nt < 4; nt++)
                    m = fmaxf(m, fmaxf(acc[mt][nt][h * 2], acc[mt][nt][h * 2 + 1]));
                int lr = wm * 32 + mt * 16 + h * 8 + (lane >> 2);
                atomicMax(&s_runmax[lr], encf(m * 0.125f));
            }
        __syncthreads();

        unsigned pm[2][2];
#pragma unroll
        for (int mt = 0; mt < 2; mt++)
#pragma unroll
            for (int h = 0; h < 2; h++) {
                int lr = wm * 32 + mt * 16 + h * 8 + (lane >> 2);
                float thr = decf(s_runmax[lr]) - 2.0f;
                unsigned msk = 0;
#pragma unroll
                for (int nt = 0; nt < 4; nt++)
#pragma unroll
                    for (int ic = 0; ic < 2; ic++)
                        if (acc[mt][nt][h * 2 + ic] * 0.125f > thr)
                            msk |= 1u << (nt * 2 + ic);
                pm[mt][h] = msk;
                s_part[lr][oid] = __popc(msk);
            }
        __syncthreads();

        if (tid < 128) {
            int b = s_cnt[tid];
#pragma unroll
            for (int o = 0; o < 16; o++) {
                int t = s_part[tid][o];
                s_part[tid][o] = b;
                b += t;
            }
            s_cnt[tid] = b;
        }
        __syncthreads();

#pragma unroll
        for (int mt = 0; mt < 2; mt++)
#pragma unroll
            for (int h = 0; h < 2; h++) {
                int lr = wm * 32 + mt * 16 + h * 8 + (lane >> 2);
                unsigned msk = pm[mt][h];
                int pos = s_part[lr][oid];
                size_t base = (rid0 + lr) * (size_t)SL;
#pragma unroll
                for (int nt = 0; nt < 4; nt++)
#pragma unroll
                    for (int ic = 0; ic < 2; ic++) {
                        if (msk & (1u << (nt * 2 + ic))) {
                            int col = c * 128 + wn * 32 + nt * 8 + (lane & 3) * 2 + ic;
                            g_cand[base + pos] = make_float2(
                                acc[mt][nt][h * 2 + ic] * 0.125f,
                                __int_as_float(col));
                            pos++;
                        }
                        acc[mt][nt][h * 2 + ic] = 0.f;
                    }
            }
    }

    __syncthreads();
    if (tid < 128) g_cnt[rid0 + tid] = s_cnt[tid];
}

// ---------------------------------------------------------------------------
// k2: entmax on candidates + sparse P*V. One warp per row, 128thr blocks.
// ---------------------------------------------------------------------------
#define NT2  128
#define NEWT 5
#define NCF  3
#define CAPL 128
#define REGC 8            // 256 reg-resident candidates (covers ~all rows)

__global__ void __launch_bounds__(NT2, 9)
entmax_pv3_kernel(const float* __restrict__ v, float* __restrict__ out)
{
    __shared__ float2 spi[4][CAPL];   // (p, key-bits) fused list

    const int tid = threadIdx.x, warp = tid >> 5, lane = tid & 31;
    const int rid = blockIdx.x * 4 + warp;
    const int cnt = g_cnt[rid];
    const float2* __restrict__ cand = g_cand + (size_t)rid * SL;
    const float* __restrict__ vb = v + (size_t)(rid >> 11) * SL * DD;

    float xs[REGC];
#pragma unroll
    for (int j = 0; j < REGC; j++) {
        int idx = j * 32 + lane;
        xs[j] = (idx < cnt) ? cand[idx].x : -1e30f;
    }
    const bool big = (cnt > REGC * 32);

    float mx = -3e38f;
#pragma unroll
    for (int j = 0; j < REGC; j++) mx = fmaxf(mx, xs[j]);
    if (big)
        for (int idx = REGC * 32 + lane; idx < cnt; idx += 32)
            mx = fmaxf(mx, cand[idx].x);
#pragma unroll
    for (int o = 16; o; o >>= 1)
        mx = fmaxf(mx, __shfl_xor_sync(0xffffffffu, mx, o));
#pragma unroll
    for (int j = 0; j < REGC; j++) xs[j] = (xs[j] - mx) * 0.5f;

    // Newton from below (tau0 = -1 guarantees f >= 1; non-candidates have
    // x <= -1 <= tau and contribute exactly 0 -> result is exact)
    float tau = -1.0f;
    for (int it = 0; it < NEWT; it++) {
        float f = 0.f, g = 0.f;
#pragma unroll
        for (int j = 0; j < REGC; j++) {
            float m = fmaxf(xs[j] - tau, 0.f);
            f = fmaf(m, m, f); g += m;
        }
        if (big)
            for (int idx = REGC * 32 + lane; idx < cnt; idx += 32) {
                float xv = (cand[idx].x - mx) * 0.5f;
                float m = fmaxf(xv - tau, 0.f);
                f = fmaf(m, m, f); g += m;
            }
#pragma unroll
        for (int o = 16; o; o >>= 1) {
            f += __shfl_xor_sync(0xffffffffu, f, o);
            g += __shfl_xor_sync(0xffffffffu, g, o);
        }
        tau += (f - 1.0f) / fmaxf(2.0f * g, 1e-20f);
    }

    // closed-form refinement on current support (exact fixed point)
    for (int p = 0; p < NCF; p++) {
        float n = 0.f, s = 0.f, qq = 0.f;
#pragma unroll
        for (int j = 0; j < REGC; j++) {
            if (xs[j] > tau) { n += 1.f; s += xs[j]; qq = fmaf(xs[j], xs[j], qq); }
        }
        if (big)
            for (int idx = REGC * 32 + lane; idx < cnt; idx += 32) {
                float xv = (cand[idx].x - mx) * 0.5f;
                if (xv > tau) { n += 1.f; s += xv; qq = fmaf(xv, xv, qq); }
            }
#pragma unroll
        for (int o = 16; o; o >>= 1) {
            n  += __shfl_xor_sync(0xffffffffu, n, o);
            s  += __shfl_xor_sync(0xffffffffu, s, o);
            qq += __shfl_xor_sync(0xffffffffu, qq, o);
        }
        float disc = fmaxf(s * s - n * (qq - 1.0f), 0.f);
        tau = (s - sqrtf(disc)) / fmaxf(n, 1.0f);
    }

    // support extraction (ballot-compacted, deterministic order) + V gather
    float2 acc = make_float2(0.f, 0.f);
    float ps = 0.f;
    const unsigned lt = (1u << lane) - 1u;
    int off = 0;

#pragma unroll
    for (int j = 0; j < REGC; j++) {
        float m = xs[j] - tau;
        bool act = (m > 0.f);
        unsigned mask = __ballot_sync(0xffffffffu, act);
        int c = __popc(mask);
        if (off + c > CAPL) {
            __syncwarp();
            for (int t = 0; t < off; t++) {
                float2 e = spi[warp][t];
                int key = __float_as_int(e.y);
                float2 vv = *(const float2*)(vb + key * DD + 2 * lane);
                acc.x = fmaf(e.x, vv.x, acc.x);
                acc.y = fmaf(e.x, vv.y, acc.y);
            }
            __syncwarp();
            off = 0;
        }
        if (act) {
            int pos = off + __popc(mask & lt);
            float pv = m * m;
            spi[warp][pos] = make_float2(pv, cand[j * 32 + lane].y);
            ps += pv;
        }
        off += c;
    }
    if (big) {
        for (int bix = REGC * 32; bix < cnt; bix += 32) {
            int idx = bix + lane;
            bool valid = idx < cnt;
            float2 t2 = valid ? cand[idx] : make_float2(-1e30f, 0.f);
            float m = (t2.x - mx) * 0.5f - tau;
            bool act = valid && (m > 0.f);
            unsigned mask = __ballot_sync(0xffffffffu, act);
            int c = __popc(mask);
            if (off + c > CAPL) {
                __syncwarp();
                for (int t = 0; t < off; t++) {
                    float2 e = spi[warp][t];
                    int key = __float_as_int(e.y);
                    float2 vv = *(const float2*)(vb + key * DD + 2 * lane);
                    acc.x = fmaf(e.x, vv.x, acc.x);
                    acc.y = fmaf(e.x, vv.y, acc.y);
                }
                __syncwarp();
                off = 0;
            }
            if (act) {
                int pos = off + __popc(mask & lt);
                float pv = m * m;
                spi[warp][pos] = make_float2(pv, t2.y);
                ps += pv;
            }
            off += c;
        }
    }
    __syncwarp();
    for (int t = 0; t < off; t++) {
        float2 e = spi[warp][t];
        int key = __float_as_int(e.y);
        float2 vv = *(const float2*)(vb + key * DD + 2 * lane);
        acc.x = fmaf(e.x, vv.x, acc.x);
        acc.y = fmaf(e.x, vv.y, acc.y);
    }

    // renormalize (first-order tau error cancellation)
#pragma unroll
    for (int o = 16; o; o >>= 1)
        ps += __shfl_xor_sync(0xffffffffu, ps, o);
    float inv = 1.0f / fmaxf(ps, 1e-20f);

    float* orow = out + (size_t)rid * DD;
    *(float2*)(orow + 2 * lane) = make_float2(acc.x * inv, acc.y * inv);
}

// ---------------------------------------------------------------------------
extern "C" void kernel_launch(void* const* d_in, const int* in_sizes, int n_in,
                              void* d_out, int out_size)
{
    const float* q = (const float*)d_in[0];
    const float* k = (const float*)d_in[1];
    const float* v = (const float*)d_in[2];
    float* out = (float*)d_out;

    dummy_kernel<<<1, 32>>>();    // capture-slot shifters: observed capture
    dummy_kernel2<<<1, 32>>>();   // lands on launch idx 3 -> qk_mma below

    prep_kernel<<<2048, 256>>>(q, k);

    cudaFuncSetAttribute(qk_mma_kernel,
                         cudaFuncAttributeMaxDynamicSharedMemorySize, SMEM1_TOTAL);
    dim3 g1(SL / 128, NBH);
    qk_mma_kernel<<<g1, NT1, SMEM1_TOTAL>>>();

    entmax_pv3_kernel<<<(NBH * SL) / 4, NT2>>>(v, out);
}